// round 6
// baseline (speedup 1.0000x reference)
#include <cuda_runtime.h>

#define FULLMASK 0xffffffffu
#define NEGC (-1000000000.0f)
#define FLR  (1e-30f)

__device__ __forceinline__ float lse2(float a, float b) {
    float mx = fmaxf(a, b);
    float mn = fminf(a, b);
    return mx + __logf(1.0f + __expf(mn - mx));
}

// ---------------------------------------------------------------------------
// Forward: one warp per CTA handles TWO batches (b0, b0+1) interleaved.
// Lane owns columns 4*lane..4*lane+3. alpha written to out buffer (native
// [B,N,M,3] layout, coalesced float4 I/O).
// ---------------------------------------------------------------------------
__global__ void __launch_bounds__(32, 1)
fwd_kernel(const float* __restrict__ theta, const float* __restrict__ Aall,
           float* __restrict__ alpha)
{
    const int lane = threadIdx.x;
    const int b0 = blockIdx.x * 2;
    const int fo = lane * 3;

    const float4* thp[2];
    float4* alp[2];
    float eM[2][3], eX[2][3];           // exp(A[:,0]) and exp(A[:,1])
    float A02[2], A12[2], A22[2];
#pragma unroll
    for (int u = 0; u < 2; u++) {
        const float* Ab = Aall + (size_t)(b0 + u) * 9;
        eM[u][0] = __expf(Ab[0]); eM[u][1] = __expf(Ab[3]); eM[u][2] = __expf(Ab[6]);
        eX[u][0] = __expf(Ab[1]); eX[u][1] = __expf(Ab[4]); eX[u][2] = __expf(Ab[7]);
        A02[u] = Ab[2]; A12[u] = Ab[5]; A22[u] = Ab[8];
        size_t base = (size_t)(b0 + u) * 49152;
        thp[u] = reinterpret_cast<const float4*>(theta + base);
        alp[u] = reinterpret_cast<float4*>(alpha + base);
    }

    float pm[2][4], px[2][4], py[2][4];
#pragma unroll
    for (int u = 0; u < 2; u++)
#pragma unroll
        for (int k = 0; k < 4; k++) { pm[u][k] = NEGC; px[u][k] = NEGC; py[u][k] = NEGC; }

    float4 t0[2], t1[2], t2[2];
#pragma unroll
    for (int u = 0; u < 2; u++) { t0[u] = thp[u][fo]; t1[u] = thp[u][fo + 1]; t2[u] = thp[u][fo + 2]; }

    for (int i = 0; i < 128; i++) {
        float4 n0[2], n1[2], n2[2];
        if (i < 127) {
            int r2 = (i + 1) * 96 + fo;
#pragma unroll
            for (int u = 0; u < 2; u++) { n0[u] = thp[u][r2]; n1[u] = thp[u][r2 + 1]; n2[u] = thp[u][r2 + 2]; }
        }
        float tf[2][12];
#pragma unroll
        for (int u = 0; u < 2; u++) {
            *reinterpret_cast<float4*>(&tf[u][0]) = t0[u];
            *reinterpret_cast<float4*>(&tf[u][4]) = t1[u];
            *reinterpret_cast<float4*>(&tf[u][8]) = t2[u];
        }

        // shared-exp representation of prev-row triples
        float mr[2][4], Em[2][4], Ex[2][4], Ey[2][4];
#pragma unroll
        for (int u = 0; u < 2; u++)
#pragma unroll
            for (int k = 0; k < 4; k++) {
                float r = fmaxf(fmaxf(pm[u][k], px[u][k]), py[u][k]);
                mr[u][k] = r;
                Em[u][k] = __expf(pm[u][k] - r);
                Ex[u][k] = __expf(px[u][k] - r);
                Ey[u][k] = __expf(py[u][k] - r);
            }
        float mrn[2], Emn[2], Exn[2], Eyn[2];
#pragma unroll
        for (int u = 0; u < 2; u++) {
            mrn[u] = __shfl_up_sync(FULLMASK, mr[u][3], 1);
            Emn[u] = __shfl_up_sync(FULLMASK, Em[u][3], 1);
            Exn[u] = __shfl_up_sync(FULLMASK, Ex[u][3], 1);
            Eyn[u] = __shfl_up_sync(FULLMASK, Ey[u][3], 1);
            if (lane == 0) { mrn[u] = NEGC; Emn[u] = 0.f; Exn[u] = 0.f; Eyn[u] = 0.f; }
        }

        float m[2][4], x[2][4];
#pragma unroll
        for (int u = 0; u < 2; u++)
#pragma unroll
            for (int k = 0; k < 4; k++) {
                float rm = k ? mr[u][k - 1] : mrn[u];
                float em = k ? Em[u][k - 1] : Emn[u];
                float ex = k ? Ex[u][k - 1] : Exn[u];
                float ey = k ? Ey[u][k - 1] : Eyn[u];
                float dotm = fmaf(eM[u][0], em, fmaf(eM[u][1], ex, fmaf(eM[u][2], ey, FLR)));
                float lm = rm + __logf(dotm);
                if (i == 0 && lane == 0 && k == 0) lm = 0.0f;     // start cell
                m[u][k] = tf[u][3 * k] + lm;
                float dotx = fmaf(eX[u][0], Em[u][k], fmaf(eX[u][1], Ex[u][k], fmaf(eX[u][2], Ey[u][k], FLR)));
                x[u][k] = tf[u][3 * k + 1] + mr[u][k] + __logf(dotx);
            }

        float mnb[2], xnb[2];
#pragma unroll
        for (int u = 0; u < 2; u++) {
            mnb[u] = __shfl_up_sync(FULLMASK, m[u][3], 1);
            xnb[u] = __shfl_up_sync(FULLMASK, x[u][3], 1);
            if (lane == 0) { mnb[u] = NEGC; xnb[u] = NEGC; }
        }

        float c[2][4], d[2][4];
#pragma unroll
        for (int u = 0; u < 2; u++)
#pragma unroll
            for (int k = 0; k < 4; k++) {
                float mL = k ? m[u][k - 1] : mnb[u];
                float xL = k ? x[u][k - 1] : xnb[u];
                c[u][k] = tf[u][3 * k + 2] + lse2(mL + A02[u], xL + A12[u]);
                d[u][k] = tf[u][3 * k + 2] + A22[u];
            }

        // inclusive prefix ops (depth-2 tree)
        float IC[2][4], ID[2][4];
#pragma unroll
        for (int u = 0; u < 2; u++) {
            IC[u][0] = c[u][0];                              ID[u][0] = d[u][0];
            IC[u][1] = lse2(c[u][1], d[u][1] + c[u][0]);     ID[u][1] = d[u][0] + d[u][1];
            float o23 = lse2(c[u][3], d[u][3] + c[u][2]);
            IC[u][2] = lse2(c[u][2], d[u][2] + IC[u][1]);    ID[u][2] = ID[u][1] + d[u][2];
            IC[u][3] = lse2(o23, (d[u][2] + d[u][3]) + IC[u][1]);  ID[u][3] = ID[u][2] + d[u][3];
        }

        float C[2], D[2];
#pragma unroll
        for (int u = 0; u < 2; u++) { C[u] = IC[u][3]; D[u] = ID[u][3]; }
#pragma unroll
        for (int off = 1; off < 32; off <<= 1) {
#pragma unroll
            for (int u = 0; u < 2; u++) {
                float Cu = __shfl_up_sync(FULLMASK, C[u], off);
                float Du = __shfl_up_sync(FULLMASK, D[u], off);
                if (lane >= off) { C[u] = lse2(C[u], D[u] + Cu); D[u] += Du; }
            }
        }
        float yin[2];
#pragma unroll
        for (int u = 0; u < 2; u++) {
            float Ce = __shfl_up_sync(FULLMASK, C[u], 1);
            float De = __shfl_up_sync(FULLMASK, D[u], 1);
            yin[u] = (lane == 0) ? NEGC : lse2(Ce, De + NEGC);
        }

        float y[2][4];
#pragma unroll
        for (int u = 0; u < 2; u++)
#pragma unroll
            for (int k = 0; k < 4; k++) y[u][k] = lse2(IC[u][k], ID[u][k] + yin[u]);

        int wo = i * 96 + fo;
#pragma unroll
        for (int u = 0; u < 2; u++) {
            alp[u][wo]     = make_float4(m[u][0], x[u][0], y[u][0], m[u][1]);
            alp[u][wo + 1] = make_float4(x[u][1], y[u][1], m[u][2], x[u][2]);
            alp[u][wo + 2] = make_float4(y[u][2], m[u][3], x[u][3], y[u][3]);
        }
#pragma unroll
        for (int u = 0; u < 2; u++)
#pragma unroll
            for (int k = 0; k < 4; k++) { pm[u][k] = m[u][k]; px[u][k] = x[u][k]; py[u][k] = y[u][k]; }
        if (i < 127) {
#pragma unroll
            for (int u = 0; u < 2; u++) { t0[u] = n0[u]; t1[u] = n1[u]; t2[u] = n2[u]; }
        }
    }
}

// ---------------------------------------------------------------------------
// Backward + combine: one warp per CTA, two batches interleaved.
// Lane scan-position p = 4*lane+k maps to column 127-p. Writes
// out = (alpha + beta) - logZ in place.
// ---------------------------------------------------------------------------
__global__ void __launch_bounds__(32, 1)
bwd_kernel(const float* __restrict__ theta, const float* __restrict__ Aall,
           float* __restrict__ out)
{
    const int lane = threadIdx.x;
    const int b0 = blockIdx.x * 2;
    const int fo = (31 - lane) * 3;

    const float4* thp[2];
    float4* op[2];
    float eB[2][9];
    float A20[2], A21[2], A22[2], logZ[2];
#pragma unroll
    for (int u = 0; u < 2; u++) {
        const float* Ab = Aall + (size_t)(b0 + u) * 9;
#pragma unroll
        for (int t = 0; t < 9; t++) eB[u][t] = __expf(Ab[t]);
        A20[u] = Ab[6]; A21[u] = Ab[7]; A22[u] = Ab[8];
        size_t base = (size_t)(b0 + u) * 49152;
        thp[u] = reinterpret_cast<const float4*>(theta + base);
        op[u]  = reinterpret_cast<float4*>(out + base);
        float la0 = out[base + 49149], la1 = out[base + 49150], la2 = out[base + 49151];
        float r = fmaxf(fmaxf(la0, la1), la2);
        logZ[u] = r + __logf(__expf(la0 - r) + __expf(la1 - r) + __expf(la2 - r));
    }

    float u0p[2][4], u1p[2][4];
#pragma unroll
    for (int u = 0; u < 2; u++)
#pragma unroll
        for (int k = 0; k < 4; k++) { u0p[u][k] = NEGC; u1p[u][k] = NEGC; }

    float4 t0[2], t1[2], t2[2];
    {
        int r0 = 127 * 96 + fo;
#pragma unroll
        for (int u = 0; u < 2; u++) { t0[u] = thp[u][r0]; t1[u] = thp[u][r0 + 1]; t2[u] = thp[u][r0 + 2]; }
    }

    for (int i = 127; i >= 0; i--) {
        const int ro = i * 96 + fo;
        // current-row alpha: single-buffered load at top (consumed at end)
        float4 a0[2], a1[2], a2[2];
#pragma unroll
        for (int u = 0; u < 2; u++) { a0[u] = op[u][ro]; a1[u] = op[u][ro + 1]; a2[u] = op[u][ro + 2]; }
        // prefetch next row theta
        float4 n0[2], n1[2], n2[2];
        if (i > 0) {
            int r2 = (i - 1) * 96 + fo;
#pragma unroll
            for (int u = 0; u < 2; u++) { n0[u] = thp[u][r2]; n1[u] = thp[u][r2 + 1]; n2[u] = thp[u][r2 + 2]; }
        }
        float tf[2][12], af[2][12];
#pragma unroll
        for (int u = 0; u < 2; u++) {
            *reinterpret_cast<float4*>(&tf[u][0]) = t0[u];
            *reinterpret_cast<float4*>(&tf[u][4]) = t1[u];
            *reinterpret_cast<float4*>(&tf[u][8]) = t2[u];
            *reinterpret_cast<float4*>(&af[u][0]) = a0[u];
            *reinterpret_cast<float4*>(&af[u][4]) = a1[u];
            *reinterpret_cast<float4*>(&af[u][8]) = a2[u];
        }

        float u0n[2];
#pragma unroll
        for (int u = 0; u < 2; u++) {
            u0n[u] = __shfl_up_sync(FULLMASK, u0p[u][3], 1);
            if (lane == 0) u0n[u] = NEGC;
        }

        const bool lastrow = (i == 127);
        float c[2][4], d[2][4], ud0[2][4];
#pragma unroll
        for (int u = 0; u < 2; u++)
#pragma unroll
            for (int k = 0; k < 4; k++) {
                const int q = 3 - k;
                float uu0 = k ? u0p[u][k - 1] : u0n[u];
                ud0[u][k] = uu0;
                float t2k = tf[u][3 * q + 2];
                c[u][k] = t2k + lse2(A20[u] + uu0, A21[u] + u1p[u][k]);
                d[u][k] = t2k + A22[u];
            }
        if (lastrow && lane == 0) {
#pragma unroll
            for (int u = 0; u < 2; u++) { c[u][0] = tf[u][11]; d[u][0] = NEGC; }  // beta(N-1,M-1)=0
        }

        float IC[2][4], ID[2][4];
#pragma unroll
        for (int u = 0; u < 2; u++) {
            IC[u][0] = c[u][0];                              ID[u][0] = d[u][0];
            IC[u][1] = lse2(c[u][1], d[u][1] + c[u][0]);     ID[u][1] = d[u][0] + d[u][1];
            float o23 = lse2(c[u][3], d[u][3] + c[u][2]);
            IC[u][2] = lse2(c[u][2], d[u][2] + IC[u][1]);    ID[u][2] = ID[u][1] + d[u][2];
            IC[u][3] = lse2(o23, (d[u][2] + d[u][3]) + IC[u][1]);  ID[u][3] = ID[u][2] + d[u][3];
        }

        float C[2], D[2];
#pragma unroll
        for (int u = 0; u < 2; u++) { C[u] = IC[u][3]; D[u] = ID[u][3]; }
#pragma unroll
        for (int off = 1; off < 32; off <<= 1) {
#pragma unroll
            for (int u = 0; u < 2; u++) {
                float Cu = __shfl_up_sync(FULLMASK, C[u], off);
                float Du = __shfl_up_sync(FULLMASK, D[u], off);
                if (lane >= off) { C[u] = lse2(C[u], D[u] + Cu); D[u] += Du; }
            }
        }
        float yin[2];
#pragma unroll
        for (int u = 0; u < 2; u++) {
            float Ce = __shfl_up_sync(FULLMASK, C[u], 1);
            float De = __shfl_up_sync(FULLMASK, D[u], 1);
            yin[u] = (lane == 0) ? NEGC : lse2(Ce, De + NEGC);
        }

        // exclusive u2 values for each scan slot, all parallel
        float wr[2][4];
#pragma unroll
        for (int u = 0; u < 2; u++) {
            wr[u][0] = yin[u];
#pragma unroll
            for (int k = 1; k < 4; k++) wr[u][k] = lse2(IC[u][k - 1], ID[u][k - 1] + yin[u]);
        }

        float nu0[2][4], nu1[2][4];
#pragma unroll
        for (int u = 0; u < 2; u++)
#pragma unroll
            for (int k = 0; k < 4; k++) {
                const int q = 3 - k;
                float r = fmaxf(fmaxf(ud0[u][k], u1p[u][k]), wr[u][k]);
                float E0 = __expf(ud0[u][k] - r);
                float E1 = __expf(u1p[u][k] - r);
                float E2 = __expf(wr[u][k] - r);
                float bb0 = r + __logf(fmaf(eB[u][0], E0, fmaf(eB[u][1], E1, fmaf(eB[u][2], E2, FLR))));
                float bb1 = r + __logf(fmaf(eB[u][3], E0, fmaf(eB[u][4], E1, fmaf(eB[u][5], E2, FLR))));
                float bb2 = r + __logf(fmaf(eB[u][6], E0, fmaf(eB[u][7], E1, fmaf(eB[u][8], E2, FLR))));
                if (lastrow && lane == 0 && k == 0) { bb0 = 0.0f; bb1 = 0.0f; bb2 = 0.0f; }
                af[u][3 * q + 0] = (af[u][3 * q + 0] + bb0) - logZ[u];
                af[u][3 * q + 1] = (af[u][3 * q + 1] + bb1) - logZ[u];
                af[u][3 * q + 2] = (af[u][3 * q + 2] + bb2) - logZ[u];
                nu0[u][k] = bb0 + tf[u][3 * q + 0];
                nu1[u][k] = bb1 + tf[u][3 * q + 1];
            }

#pragma unroll
        for (int u = 0; u < 2; u++) {
            op[u][ro]     = *reinterpret_cast<float4*>(&af[u][0]);
            op[u][ro + 1] = *reinterpret_cast<float4*>(&af[u][4]);
            op[u][ro + 2] = *reinterpret_cast<float4*>(&af[u][8]);
        }
#pragma unroll
        for (int u = 0; u < 2; u++)
#pragma unroll
            for (int k = 0; k < 4; k++) { u0p[u][k] = nu0[u][k]; u1p[u][k] = nu1[u][k]; }
        if (i > 0) {
#pragma unroll
            for (int u = 0; u < 2; u++) { t0[u] = n0[u]; t1[u] = n1[u]; t2[u] = n2[u]; }
        }
    }
}

extern "C" void kernel_launch(void* const* d_in, const int* in_sizes, int n_in,
                              void* d_out, int out_size)
{
    const float* theta = (const float*)d_in[0];
    const float* A     = (const float*)d_in[1];
    float* out         = (float*)d_out;
    int B = in_sizes[1] / 9;   // 256
    fwd_kernel<<<B / 2, 32>>>(theta, A, out);
    bwd_kernel<<<B / 2, 32>>>(theta, A, out);
}

// round 7
// speedup vs baseline: 1.8138x; 1.8138x over previous
#include <cuda_runtime.h>

#define FULLMASK 0xffffffffu
#define NEGC (-1000000000.0f)
#define FLR  (1e-30f)

__device__ __forceinline__ float lse2(float a, float b) {
    float mx = fmaxf(a, b);
    float mn = fminf(a, b);
    return mx + __logf(1.0f + __expf(mn - mx));
}
__device__ __forceinline__ float fmax3(float a, float b, float c) {
    return fmaxf(fmaxf(a, b), c);
}
__device__ __forceinline__ void relstore(int* p, int v) {
    asm volatile("st.release.cta.b32 [%0], %1;" :: "l"(p), "r"(v) : "memory");
}
__device__ __forceinline__ int acqload(int* p) {
    int v; asm volatile("ld.acquire.cta.b32 %0, [%1];" : "=r"(v) : "l"(p) : "memory");
    return v;
}

// One CTA (2 warps) per batch. Warp 0 owns columns 0..63, warp 1 owns 64..127.
// Fwd: warp0 is the free-running producer (left->right chain), warp1 trails via
// a per-row mailbox (m,x,y at col 63). Bwd: roles swap (warp1 produces u0/u2 at
// col 64). Fused fwd+bwd; logZ handed through shared memory.
__global__ void __launch_bounds__(64, 1)
fb_kernel(const float* __restrict__ theta, const float* __restrict__ Aall,
          float* __restrict__ out)
{
    __shared__ float mbm[128], mbx[128], mby[128];   // fwd mailbox (col 63)
    __shared__ float bu0[128], bu2[128];             // bwd mailbox (col 64)
    __shared__ int ff[128], bf[128];
    __shared__ float shlogZ;

    const int tid  = threadIdx.x;
    const int wid  = tid >> 5;
    const int lane = tid & 31;
    const bool left = (wid == 0);
    const int b = blockIdx.x;

    for (int j = tid; j < 128; j += 64) { ff[j] = 0; bf[j] = 0; }
    __syncthreads();

    const float* Ab = Aall + (size_t)b * 9;
    const float A02 = Ab[2], A12 = Ab[5], A20 = Ab[6], A21 = Ab[7], A22 = Ab[8];
    float E[9];
#pragma unroll
    for (int t = 0; t < 9; t++) E[t] = __expf(Ab[t]);
    const float eM0 = E[0], eM1 = E[3], eM2 = E[6];   // exp(A[:,0])
    const float eX0 = E[1], eX1 = E[4], eX2 = E[7];   // exp(A[:,1])

    const size_t base = (size_t)b * 49152;
    const float2* th2 = reinterpret_cast<const float2*>(theta + base);
    float2* o2 = reinterpret_cast<float2*>(out + base);

    // ====================== FORWARD ======================
    {
        const int f2 = (left ? 0 : 96) + 3 * lane;   // float2 offset in a 192-float2 row
        float pm0 = NEGC, pm1 = NEGC, px0 = NEGC, px1 = NEGC, py0 = NEGC, py1 = NEGC;
        float la0 = NEGC, la1 = NEGC, la2 = NEGC;

        float2 t0 = th2[f2], t1 = th2[f2 + 1], t2 = th2[f2 + 2];
        for (int i = 0; i < 128; i++) {
            float2 n0, n1, n2;
            if (i < 127) {
                int r = (i + 1) * 192 + f2;
                n0 = th2[r]; n1 = th2[r + 1]; n2 = th2[r + 2];
            }
            const float tf0 = t0.x, tf1 = t0.y, tf2 = t1.x;
            const float tf3 = t1.y, tf4 = t2.x, tf5 = t2.y;

            float mbmi = NEGC, mbxi = NEGC, mbyi = NEGC;
            float dM = NEGC, dX = NEGC, dY = NEGC;
            if (!left) {
                while (acqload(&ff[i]) == 0) { __nanosleep(32); }
                mbmi = mbm[i]; mbxi = mbx[i]; mbyi = mby[i];
                if (i > 0) { dM = mbm[i - 1]; dX = mbx[i - 1]; dY = mby[i - 1]; }
            }

            // shared-exp of prev-row triples (per local col)
            float r0 = fmax3(pm0, px0, py0), r1 = fmax3(pm1, px1, py1);
            float Em0 = __expf(pm0 - r0), Ex0 = __expf(px0 - r0), Ey0 = __expf(py0 - r0);
            float Em1 = __expf(pm1 - r1), Ex1 = __expf(px1 - r1), Ey1 = __expf(py1 - r1);
            // neighbor (col-1) prev-row triple
            float rs  = __shfl_up_sync(FULLMASK, r1, 1);
            float Ems = __shfl_up_sync(FULLMASK, Em1, 1);
            float Exs = __shfl_up_sync(FULLMASK, Ex1, 1);
            float Eys = __shfl_up_sync(FULLMASK, Ey1, 1);
            if (lane == 0) {
                if (left) { rs = NEGC; Ems = 0.f; Exs = 0.f; Eys = 0.f; }
                else {
                    rs = fmax3(dM, dX, dY);
                    Ems = __expf(dM - rs); Exs = __expf(dX - rs); Eys = __expf(dY - rs);
                }
            }

            float lm0 = rs + __logf(fmaf(eM0, Ems, fmaf(eM1, Exs, fmaf(eM2, Eys, FLR))));
            if (left && i == 0 && lane == 0) lm0 = 0.0f;   // start cell (0,0,match)
            float m0 = tf0 + lm0;
            float x0 = tf1 + r0 + __logf(fmaf(eX0, Em0, fmaf(eX1, Ex0, fmaf(eX2, Ey0, FLR))));
            float m1 = tf3 + r0 + __logf(fmaf(eM0, Em0, fmaf(eM1, Ex0, fmaf(eM2, Ey0, FLR))));
            float x1 = tf4 + r1 + __logf(fmaf(eX0, Em1, fmaf(eX1, Ex1, fmaf(eX2, Ey1, FLR))));

            // y-chain ops
            float mnb = __shfl_up_sync(FULLMASK, m1, 1);
            float xnb = __shfl_up_sync(FULLMASK, x1, 1);
            if (lane == 0) {
                if (left) { mnb = NEGC; xnb = NEGC; }
                else      { mnb = mbmi; xnb = mbxi; }
            }
            float c0 = tf2 + lse2(mnb + A02, xnb + A12);
            float c1 = tf5 + lse2(m0 + A02, x0 + A12);
            float d0 = tf2 + A22, d1 = tf5 + A22;
            float IC1 = lse2(c1, d1 + c0), ID1 = d0 + d1;

            float C = IC1, D = ID1;
#pragma unroll
            for (int off = 1; off < 32; off <<= 1) {
                float Cu = __shfl_up_sync(FULLMASK, C, off);
                float Du = __shfl_up_sync(FULLMASK, D, off);
                if (lane >= off) { C = lse2(C, D + Cu); D += Du; }
            }
            float Ce = __shfl_up_sync(FULLMASK, C, 1);
            float De = __shfl_up_sync(FULLMASK, D, 1);
            float yin;
            if (left) yin = (lane == 0) ? NEGC : lse2(Ce, De + NEGC);
            else      yin = (lane == 0) ? mbyi : lse2(Ce, De + mbyi);

            float y0 = lse2(c0, d0 + yin);
            float y1 = lse2(IC1, ID1 + yin);

            int wo = i * 192 + f2;
            o2[wo]     = make_float2(m0, x0);
            o2[wo + 1] = make_float2(y0, m1);
            o2[wo + 2] = make_float2(x1, y1);

            if (left && lane == 31) {
                mbm[i] = m1; mbx[i] = x1; mby[i] = y1;
                relstore(&ff[i], 1);
            }
            if (!left && i == 127) { la0 = m1; la1 = x1; la2 = y1; }

            pm0 = m0; pm1 = m1; px0 = x0; px1 = x1; py0 = y0; py1 = y1;
            if (i < 127) { t0 = n0; t1 = n1; t2 = n2; }
        }
        if (!left) {   // logZ from alpha(127,127,:) held in lane31
            la0 = __shfl_sync(FULLMASK, la0, 31);
            la1 = __shfl_sync(FULLMASK, la1, 31);
            la2 = __shfl_sync(FULLMASK, la2, 31);
            float r = fmax3(la0, la1, la2);
            float lz = r + __logf(__expf(la0 - r) + __expf(la1 - r) + __expf(la2 - r));
            // stash in a register for the bwd phase via shared (also for warp0)
            if (lane == 31) shlogZ = lz;   // published with bf[127] release below
        }
    }

    // ====================== BACKWARD + COMBINE ======================
    {
        // warp1 (right half) is now the producer: scan slots 0..63 <-> cols 127..64.
        // warp0 (left half) consumes: slots 64..127 <-> cols 63..0.
        const int f2 = (left ? 93 : 189) - 3 * lane;
        // slot k0 col = (left? 63-2l : 127-2l) -> floats tf[3..5]; slot k1 col-1 -> tf[0..2]
        float u0p0 = NEGC, u0p1 = NEGC, u1p0 = NEGC, u1p1 = NEGC;
        float logZ = 0.f;
        if (!left) logZ = shlogZ;   // same warp wrote it (warp-synchronous after shfl)

        float2 t0 = th2[127 * 192 + f2], t1 = th2[127 * 192 + f2 + 1], t2 = th2[127 * 192 + f2 + 2];
        for (int i = 127; i >= 0; i--) {
            const int ro = i * 192 + f2;
            float2 a0 = o2[ro], a1 = o2[ro + 1], a2 = o2[ro + 2];
            float2 n0, n1, n2;
            if (i > 0) {
                int r = (i - 1) * 192 + f2;
                n0 = th2[r]; n1 = th2[r + 1]; n2 = th2[r + 2];
            }
            const float tf0 = t0.x, tf1 = t0.y, tf2v = t1.x;
            const float tf3 = t1.y, tf4 = t2.x, tf5 = t2.y;
            float af0 = a0.x, af1 = a0.y, af2 = a1.x, af3 = a1.y, af4 = a2.x, af5 = a2.y;

            float seed = NEGC, u0ext = NEGC;
            if (left) {
                while (acqload(&bf[i]) == 0) { __nanosleep(32); }
                if (i == 127) logZ = shlogZ;
                seed = bu2[i];
                u0ext = (i < 127) ? bu0[i + 1] : NEGC;
            }

            float u0n = __shfl_up_sync(FULLMASK, u0p1, 1);
            if (lane == 0) u0n = left ? u0ext : NEGC;

            const bool lastrow = (i == 127);
            float c0 = tf5  + lse2(A20 + u0n,  A21 + u1p0);
            float c1 = tf2v + lse2(A20 + u0p0, A21 + u1p1);
            float d0 = tf5 + A22, d1 = tf2v + A22;
            if (!left && lastrow && lane == 0) { c0 = tf5; d0 = NEGC; }  // beta(127,127)=0
            float IC1 = lse2(c1, d1 + c0), ID1 = d0 + d1;

            float C = IC1, D = ID1;
#pragma unroll
            for (int off = 1; off < 32; off <<= 1) {
                float Cu = __shfl_up_sync(FULLMASK, C, off);
                float Du = __shfl_up_sync(FULLMASK, D, off);
                if (lane >= off) { C = lse2(C, D + Cu); D += Du; }
            }
            float Ce = __shfl_up_sync(FULLMASK, C, 1);
            float De = __shfl_up_sync(FULLMASK, D, 1);
            float yin;
            if (!left) yin = (lane == 0) ? NEGC : lse2(Ce, De + NEGC);
            else       yin = (lane == 0) ? seed : lse2(Ce, De + seed);

            float wr0 = yin;
            float wr1 = lse2(c0, d0 + yin);

            // slot k0  (cols 63-2l / 127-2l), theta slots tf3..tf5
            float rr = fmax3(u0n, u1p0, wr0);
            float e0 = __expf(u0n - rr), e1 = __expf(u1p0 - rr), e2 = __expf(wr0 - rr);
            float bb0 = rr + __logf(fmaf(E[0], e0, fmaf(E[1], e1, fmaf(E[2], e2, FLR))));
            float bb1 = rr + __logf(fmaf(E[3], e0, fmaf(E[4], e1, fmaf(E[5], e2, FLR))));
            float bb2 = rr + __logf(fmaf(E[6], e0, fmaf(E[7], e1, fmaf(E[8], e2, FLR))));
            if (!left && lastrow && lane == 0) { bb0 = 0.f; bb1 = 0.f; bb2 = 0.f; }
            af3 = (af3 + bb0) - logZ;
            af4 = (af4 + bb1) - logZ;
            af5 = (af5 + bb2) - logZ;
            float nu00 = bb0 + tf3, nu10 = bb1 + tf4;

            // slot k1
            rr = fmax3(u0p0, u1p1, wr1);
            e0 = __expf(u0p0 - rr); e1 = __expf(u1p1 - rr); e2 = __expf(wr1 - rr);
            float cb0 = rr + __logf(fmaf(E[0], e0, fmaf(E[1], e1, fmaf(E[2], e2, FLR))));
            float cb1 = rr + __logf(fmaf(E[3], e0, fmaf(E[4], e1, fmaf(E[5], e2, FLR))));
            float cb2 = rr + __logf(fmaf(E[6], e0, fmaf(E[7], e1, fmaf(E[8], e2, FLR))));
            af0 = (af0 + cb0) - logZ;
            af1 = (af1 + cb1) - logZ;
            af2 = (af2 + cb2) - logZ;
            float nu01 = cb0 + tf0, nu11 = cb1 + tf1;

            o2[ro]     = make_float2(af0, af1);
            o2[ro + 1] = make_float2(af2, af3);
            o2[ro + 2] = make_float2(af4, af5);

            if (!left && lane == 31) {
                float u2incl = lse2(IC1, ID1 + yin);   // u2 at col 64 (inclusive)
                bu0[i] = nu01;                         // u0 at col 64, this row
                bu2[i] = u2incl;
                relstore(&bf[i], 1);
            }
            u0p0 = nu00; u0p1 = nu01; u1p0 = nu10; u1p1 = nu11;
            if (i > 0) { t0 = n0; t1 = n1; t2 = n2; }
        }
    }
}

extern "C" void kernel_launch(void* const* d_in, const int* in_sizes, int n_in,
                              void* d_out, int out_size)
{
    const float* theta = (const float*)d_in[0];
    const float* A     = (const float*)d_in[1];
    float* out         = (float*)d_out;
    int B = in_sizes[1] / 9;   // 256
    fb_kernel<<<B, 64>>>(theta, A, out);
}